// round 7
// baseline (speedup 1.0000x reference)
#include <cuda_runtime.h>

#define MAXN 100000
#define HID 64
#define CAP 64   // neighbor-list capacity per node (deg ~ Poisson(16))

// Scratch (no cudaMalloc allowed)
__device__ float g_bufY[(size_t)MAXN * HID];    // 25.6 MB
__device__ float g_bufAgg[(size_t)MAXN * HID];  // 25.6 MB
__device__ int   g_cnt[MAXN];                   // 0.4 MB
__device__ int   g_buck[(size_t)MAXN * CAP];    // 25.6 MB

typedef unsigned long long ull;

// ---------------------------------------------------------------------------
// f32x2 packed helpers (Blackwell FFMA2 — PTX-only, 2 FMAs per issue)
// ---------------------------------------------------------------------------
__device__ __forceinline__ void fma2(ull& d, ull a, ull b) {
    asm("fma.rn.f32x2 %0, %1, %2, %0;" : "+l"(d) : "l"(a), "l"(b));
}
__device__ __forceinline__ ull pack2(float lo, float hi) {
    ull r;
    asm("mov.b64 %0, {%1, %2};" : "=l"(r) : "f"(lo), "f"(hi));
    return r;
}
__device__ __forceinline__ float2 unpack2(ull v) {
    float2 f;
    asm("mov.b64 {%0, %1}, %2;" : "=f"(f.x), "=f"(f.y) : "l"(v));
    return f;
}

// ---------------------------------------------------------------------------
// Neighbor-list build (device body): cnt[d]=in-degree, buck[d*CAP+slot]=src
// ---------------------------------------------------------------------------
__global__ void zero_cnt_kernel(int* cnt, int N) {
    int i = blockIdx.x * blockDim.x + threadIdx.x;
    if (i < N) cnt[i] = 0;
}

__device__ __forceinline__ void build_body(const int* __restrict__ ei,
                                           int* cnt, int* buck, int E, int blk) {
    int e = blk * 256 + threadIdx.x;
    if (e >= E) return;
    int s = __ldg(&ei[e]);
    int d = __ldg(&ei[E + e]);
    int slot = atomicAdd(&cnt[d], 1);
    if (slot < CAP) buck[(size_t)d * CAP + slot] = s;
}

// ---------------------------------------------------------------------------
// GEMM body: outY[64 rows of blk, 64] = act(X) @ W.
// k-pair packing: Wp[kp][c] = (W[2kp][c], W[2kp+1][c]) so both f32x2 lanes
// carry independent k-slices; X pairs (a_2kp, a_2kp+1) come free via LDS.64
// since k is contiguous in Xs. Epilogue sums the two lanes.
// Per k-pair: 8 LDS.64 + 16 FFMA2 = 22 issues vs 32 FMA-pipe cycles -> pipe-bound.
// ---------------------------------------------------------------------------
template<int K, bool PRE>
__device__ __forceinline__ void gemm_body(const float* X,
                                          const float* __restrict__ W,
                                          const float* __restrict__ bpre,
                                          float* __restrict__ outY,
                                          int N, int blk) {
    constexpr int LD = K + 4;            // floats; keeps 8B alignment (LD even)
    constexpr int KV = K / 4;
    extern __shared__ float smem[];
    float* Xs = smem;                    // [64][LD]
    ull*   Wp = (ull*)(smem + 64 * LD);  // [K/2][64] packed k-pairs

    const int tid  = threadIdx.x;
    const int row0 = blk * 64;

    // pack W into k-pair layout
    for (int i = tid; i < (K / 2) * 64; i += 256) {
        int kp = i >> 6, c = i & 63;
        float w0 = __ldg(&W[(2 * kp + 0) * 64 + c]);
        float w1 = __ldg(&W[(2 * kp + 1) * 64 + c]);
        Wp[i] = pack2(w0, w1);
    }
    // X tile, optional fused relu(x+b)
    for (int i = tid; i < 64 * KV; i += 256) {
        int r  = i / KV;
        int c4 = i % KV;
        float4 v = make_float4(0.f, 0.f, 0.f, 0.f);
        if (row0 + r < N)
            v = *(const float4*)(X + (size_t)(row0 + r) * K + c4 * 4);
        if (PRE) {
            v.x = fmaxf(v.x + __ldg(&bpre[c4 * 4 + 0]), 0.f);
            v.y = fmaxf(v.y + __ldg(&bpre[c4 * 4 + 1]), 0.f);
            v.z = fmaxf(v.z + __ldg(&bpre[c4 * 4 + 2]), 0.f);
            v.w = fmaxf(v.w + __ldg(&bpre[c4 * 4 + 3]), 0.f);
        }
        *(float4*)(Xs + r * LD + c4 * 4) = v;
    }
    __syncthreads();

    const int tx = tid & 15;             // cols tx*4 .. tx*4+3
    const int ty = tid >> 4;             // rows ty*4 .. ty*4+3

    ull acc[4][4];
    #pragma unroll
    for (int i = 0; i < 4; ++i)
        #pragma unroll
        for (int j = 0; j < 4; ++j) acc[i][j] = 0ull;

    #pragma unroll 4
    for (int kp = 0; kp < K / 2; ++kp) {
        ull w0 = Wp[kp * 64 + tx * 4 + 0];
        ull w1 = Wp[kp * 64 + tx * 4 + 1];
        ull w2 = Wp[kp * 64 + tx * 4 + 2];
        ull w3 = Wp[kp * 64 + tx * 4 + 3];
        #pragma unroll
        for (int i = 0; i < 4; ++i) {
            ull a = *(const ull*)(Xs + (ty * 4 + i) * LD + 2 * kp);
            fma2(acc[i][0], a, w0);
            fma2(acc[i][1], a, w1);
            fma2(acc[i][2], a, w2);
            fma2(acc[i][3], a, w3);
        }
    }

    #pragma unroll
    for (int i = 0; i < 4; ++i) {
        int r = row0 + ty * 4 + i;
        if (r < N) {
            float4 o;
            float2 f0 = unpack2(acc[i][0]);
            float2 f1 = unpack2(acc[i][1]);
            float2 f2 = unpack2(acc[i][2]);
            float2 f3 = unpack2(acc[i][3]);
            o.x = f0.x + f0.y;  o.y = f1.x + f1.y;
            o.z = f2.x + f2.y;  o.w = f3.x + f3.y;
            *(float4*)(outY + (size_t)r * 64 + tx * 4) = o;
        }
    }
}

// ---------------------------------------------------------------------------
// Merged kernel: blocks [0,gb) compute gemm1 (FMA-bound), blocks [gb,..)
// build the neighbor lists (L2-atomic-bound). Complementary pipes overlap.
// ---------------------------------------------------------------------------
__global__ void gemm1_build_kernel(const float* x, const float* __restrict__ W1,
                                   float* __restrict__ bufY, int N,
                                   const int* __restrict__ ei,
                                   int* cnt, int* buck, int E, int gb) {
    if ((int)blockIdx.x < gb)
        gemm_body<128, false>(x, W1, nullptr, bufY, N, blockIdx.x);
    else
        build_body(ei, cnt, buck, E, blockIdx.x - gb);
}

__global__ void gemm2_kernel(const float* X, const float* __restrict__ W2,
                             const float* __restrict__ b1,
                             float* __restrict__ outY, int N) {
    gemm_body<64, true>(X, W2, b1, outY, N, blockIdx.x);
}

// ---------------------------------------------------------------------------
// Gather core (at LTS cap; 4-way unroll, 2 accumulators)
// ---------------------------------------------------------------------------
__device__ __forceinline__ float4 gather_row(const int* __restrict__ cnt,
                                             const int* __restrict__ buck,
                                             const float* __restrict__ Y,
                                             int n, int c) {
    float4 a0 = __ldg((const float4*)(Y + (size_t)n * 64) + c);  // self term
    float4 a1 = make_float4(0.f, 0.f, 0.f, 0.f);
    int m = min(__ldg(&cnt[n]), CAP);
    const int* b = buck + (size_t)n * CAP;

    int j = 0;
    for (; j + 4 <= m; j += 4) {
        int s0 = __ldg(&b[j]);
        int s1 = __ldg(&b[j + 1]);
        int s2 = __ldg(&b[j + 2]);
        int s3 = __ldg(&b[j + 3]);
        float4 v0 = __ldg((const float4*)(Y + (size_t)s0 * 64) + c);
        float4 v1 = __ldg((const float4*)(Y + (size_t)s1 * 64) + c);
        float4 v2 = __ldg((const float4*)(Y + (size_t)s2 * 64) + c);
        float4 v3 = __ldg((const float4*)(Y + (size_t)s3 * 64) + c);
        a0.x += v0.x + v1.x;  a0.y += v0.y + v1.y;
        a0.z += v0.z + v1.z;  a0.w += v0.w + v1.w;
        a1.x += v2.x + v3.x;  a1.y += v2.y + v3.y;
        a1.z += v2.z + v3.z;  a1.w += v2.w + v3.w;
    }
    for (; j < m; ++j) {
        int s0 = __ldg(&b[j]);
        float4 v0 = __ldg((const float4*)(Y + (size_t)s0 * 64) + c);
        a0.x += v0.x; a0.y += v0.y; a0.z += v0.z; a0.w += v0.w;
    }
    a0.x += a1.x; a0.y += a1.y; a0.z += a1.z; a0.w += a1.w;
    return a0;
}

__global__ void gather_kernel(const int* __restrict__ cnt,
                              const int* __restrict__ buck,
                              const float* __restrict__ Y,
                              float* __restrict__ Agg,
                              int N) {
    int t = blockIdx.x * blockDim.x + threadIdx.x;
    int n = t >> 4;
    int c = t & 15;
    if (n >= N) return;
    float4 acc = gather_row(cnt, buck, Y, n, c);
    *((float4*)(Agg + (size_t)n * 64) + c) = acc;
}

// ---------------------------------------------------------------------------
// Fused layer-2 aggregation + MLP head
// ---------------------------------------------------------------------------
__global__ void gather_head_kernel(const int* __restrict__ cnt,
                                   const int* __restrict__ buck,
                                   const float* __restrict__ Y,
                                   const float* __restrict__ b2,
                                   const float* __restrict__ W3,
                                   const float* __restrict__ b3,
                                   const float* __restrict__ W4,
                                   const float* __restrict__ b4,
                                   float* __restrict__ out,
                                   int N) {
    __shared__ float W3s[64 * 16];
    __shared__ float b2s[64], b3s[16], W4s[16];
    __shared__ float h2s[16][64];        // 16 nodes per 256-thread block

    const int tid = threadIdx.x;
    for (int i = tid; i < 64 * 16; i += 256) W3s[i] = W3[i];
    if (tid < 64) b2s[tid] = b2[tid];
    if (tid < 16) { b3s[tid] = b3[tid]; W4s[tid] = W4[tid]; }
    __syncthreads();

    int t = blockIdx.x * 256 + tid;
    int n = t >> 4;
    int c = t & 15;                      // float4 column / W3 output index
    int g = tid >> 4;                    // node slot within block
    if (n >= N) return;

    float4 acc = gather_row(cnt, buck, Y, n, c);

    float4 h;
    h.x = fmaxf(acc.x + b2s[4 * c + 0], 0.f);
    h.y = fmaxf(acc.y + b2s[4 * c + 1], 0.f);
    h.z = fmaxf(acc.z + b2s[4 * c + 2], 0.f);
    h.w = fmaxf(acc.w + b2s[4 * c + 3], 0.f);
    *(float4*)(&h2s[g][4 * c]) = h;
    __syncwarp();

    float a3 = b3s[c];
    #pragma unroll 16
    for (int k = 0; k < 64; ++k)
        a3 += h2s[g][k] * W3s[k * 16 + c];
    float v = fmaxf(a3, 0.f) * W4s[c];

    #pragma unroll
    for (int off = 8; off > 0; off >>= 1)
        v += __shfl_xor_sync(0xffffffffu, v, off, 16);

    if (c == 0) out[n] = v + __ldg(&b4[0]);
}

// ---------------------------------------------------------------------------
extern "C" void kernel_launch(void* const* d_in, const int* in_sizes, int n_in,
                              void* d_out, int out_size) {
    const float* x  = (const float*)d_in[0];
    const int*   ei = (const int*)d_in[1];     // int32 (JAX x64 disabled)
    const float* W1 = (const float*)d_in[2];
    const float* b1 = (const float*)d_in[3];
    const float* W2 = (const float*)d_in[4];
    const float* b2 = (const float*)d_in[5];
    const float* W3 = (const float*)d_in[6];
    const float* b3 = (const float*)d_in[7];
    const float* W4 = (const float*)d_in[8];
    const float* b4 = (const float*)d_in[9];
    float* out = (float*)d_out;

    const int N = in_sizes[0] / 128;     // 100000
    const int E = in_sizes[1] / 2;       // 1600000

    float *bufY, *bufAgg;
    int *cnt, *buck;
    cudaGetSymbolAddress((void**)&bufY, g_bufY);
    cudaGetSymbolAddress((void**)&bufAgg, g_bufAgg);
    cudaGetSymbolAddress((void**)&cnt, g_cnt);
    cudaGetSymbolAddress((void**)&buck, g_buck);

    const int smem1 = (64 * (128 + 4) + 128 * 64) * (int)sizeof(float); // 66560
    const int smem2 = (64 * (64 + 4)  + 64 * 64)  * (int)sizeof(float); // 33792
    cudaFuncSetAttribute((const void*)gemm1_build_kernel,
                         cudaFuncAttributeMaxDynamicSharedMemorySize, smem1);
    cudaFuncSetAttribute((const void*)gemm2_kernel,
                         cudaFuncAttributeMaxDynamicSharedMemorySize, smem2);

    const int gb  = (N + 63) / 64;                             // 1563 gemm blocks
    const int bb  = (E + 255) / 256;                           // 6250 build blocks
    const int agb = (int)(((long long)N * 16 + 255) / 256);

    // zero degree counters (must precede build blocks)
    zero_cnt_kernel<<<(N + 255) / 256, 256>>>(cnt, N);
    // merged: gemm1 (FMA-bound) overlapped with bucket build (L2-bound)
    gemm1_build_kernel<<<gb + bb, 256, smem1>>>(x, W1, bufY, N, ei, cnt, buck, E, gb);
    // agg1 = y1 + gather(y1)
    gather_kernel<<<agb, 256>>>(cnt, buck, bufY, bufAgg, N);
    // y2 = relu(agg1+b1)@W2
    gemm2_kernel<<<gb, 256, smem2>>>(bufAgg, W2, b1, bufY, N);
    // fused: agg2 = y2 + gather(y2); head MLP -> out
    gather_head_kernel<<<agb, 256>>>(cnt, buck, bufY, b2, W3, b3, W4, b4, out, N);
}

// round 8
// speedup vs baseline: 1.1716x; 1.1716x over previous
#include <cuda_runtime.h>

#define MAXN 100000
#define HID 64
#define CAP 64   // neighbor-list capacity per node (deg ~ Poisson(16))

// Scratch (no cudaMalloc allowed)
__device__ float g_bufY[(size_t)MAXN * HID];    // 25.6 MB
__device__ float g_bufAgg[(size_t)MAXN * HID];  // 25.6 MB
__device__ int   g_cnt[MAXN];                   // 0.4 MB
__device__ int   g_buck[(size_t)MAXN * CAP];    // 25.6 MB

typedef unsigned long long ull;

// ---------------------------------------------------------------------------
// f32x2 packed helpers (Blackwell FFMA2 — PTX-only, 2 FMAs per issue)
// ---------------------------------------------------------------------------
__device__ __forceinline__ void fma2(ull& d, ull a, ull b) {
    asm("fma.rn.f32x2 %0, %1, %2, %0;" : "+l"(d) : "l"(a), "l"(b));
}
__device__ __forceinline__ ull dup2(float a) {
    ull r;
    asm("mov.b64 %0, {%1, %1};" : "=l"(r) : "f"(a));
    return r;
}
__device__ __forceinline__ float2 unpack2(ull v) {
    float2 f;
    asm("mov.b64 {%0, %1}, %2;" : "=f"(f.x), "=f"(f.y) : "l"(v));
    return f;
}

// ---------------------------------------------------------------------------
// Neighbor-list build body: cnt[d]=in-degree, buck[d*CAP+slot]=src
// ---------------------------------------------------------------------------
__global__ void zero_cnt_kernel(int* cnt, int N) {
    int i = blockIdx.x * blockDim.x + threadIdx.x;
    if (i < N) cnt[i] = 0;
}

__device__ __forceinline__ void build_body(const int* __restrict__ ei,
                                           int* cnt, int* buck, int E, int blk) {
    int e = blk * 256 + threadIdx.x;
    if (e >= E) return;
    int s = __ldg(&ei[e]);
    int d = __ldg(&ei[E + e]);
    int slot = atomicAdd(&cnt[d], 1);
    if (slot < CAP) buck[(size_t)d * CAP + slot] = s;
}

// ---------------------------------------------------------------------------
// GEMM body (R6-proven): out[64 rows, 64] = act(X) @ W
// 256 threads, 4 rows x 4 cols micro-tile, f32x2 col-pair accumulators
// (acc[4][2] ull = 16 accumulator regs -> ~40 regs total, high occupancy).
// ---------------------------------------------------------------------------
template<int K, bool PRE>
__device__ __forceinline__ void gemm_body(const float* X,
                                          const float* __restrict__ W,
                                          const float* __restrict__ bpre,
                                          float* __restrict__ outY,
                                          int N, int blk) {
    constexpr int LD = K + 4;
    constexpr int KV = K / 4;
    extern __shared__ float smem[];
    float* Xs = smem;                    // [64][LD]
    float* Ws = smem + 64 * LD;          // [K][64]

    const int tid  = threadIdx.x;
    const int row0 = blk * 64;

    {   // W tile
        float4* Ws4 = (float4*)Ws;
        const float4* Wg4 = (const float4*)W;
        for (int i = tid; i < K * 16; i += 256) Ws4[i] = Wg4[i];
    }
    // X tile, optional fused relu(x+b)
    for (int i = tid; i < 64 * KV; i += 256) {
        int r  = i / KV;
        int c4 = i % KV;
        float4 v = make_float4(0.f, 0.f, 0.f, 0.f);
        if (row0 + r < N)
            v = *(const float4*)(X + (size_t)(row0 + r) * K + c4 * 4);
        if (PRE) {
            v.x = fmaxf(v.x + __ldg(&bpre[c4 * 4 + 0]), 0.f);
            v.y = fmaxf(v.y + __ldg(&bpre[c4 * 4 + 1]), 0.f);
            v.z = fmaxf(v.z + __ldg(&bpre[c4 * 4 + 2]), 0.f);
            v.w = fmaxf(v.w + __ldg(&bpre[c4 * 4 + 3]), 0.f);
        }
        *(float4*)(Xs + r * LD + c4 * 4) = v;
    }
    __syncthreads();

    const int tx = tid & 15;             // cols tx*4 .. tx*4+3  (2 col-pairs)
    const int ty = tid >> 4;             // rows ty*4 .. ty*4+3

    ull acc[4][2];
    #pragma unroll
    for (int i = 0; i < 4; ++i) { acc[i][0] = 0ull; acc[i][1] = 0ull; }

    const ull* Wsq = (const ull*)Ws;
    #pragma unroll 8
    for (int k = 0; k < K; ++k) {
        ull w01 = Wsq[k * 32 + tx * 2 + 0];
        ull w23 = Wsq[k * 32 + tx * 2 + 1];
        #pragma unroll
        for (int i = 0; i < 4; ++i) {
            ull aa = dup2(Xs[(ty * 4 + i) * LD + k]);
            fma2(acc[i][0], aa, w01);
            fma2(acc[i][1], aa, w23);
        }
    }

    #pragma unroll
    for (int i = 0; i < 4; ++i) {
        int r = row0 + ty * 4 + i;
        if (r < N) {
            float2 p0 = unpack2(acc[i][0]);
            float2 p1 = unpack2(acc[i][1]);
            *(float4*)(outY + (size_t)r * 64 + tx * 4) =
                make_float4(p0.x, p0.y, p1.x, p1.y);
        }
    }
}

// ---------------------------------------------------------------------------
// Merged: blocks [0,gb) run gemm1 (FMA-bound), blocks [gb,..) build the
// neighbor lists (L2-atomic-bound). Complementary pipes overlap in one wave.
// ---------------------------------------------------------------------------
__global__ void gemm1_build_kernel(const float* x, const float* __restrict__ W1,
                                   float* __restrict__ bufY, int N,
                                   const int* __restrict__ ei,
                                   int* cnt, int* buck, int E, int gb) {
    if ((int)blockIdx.x < gb)
        gemm_body<128, false>(x, W1, nullptr, bufY, N, blockIdx.x);
    else
        build_body(ei, cnt, buck, E, blockIdx.x - gb);
}

__global__ void gemm2_kernel(const float* X, const float* __restrict__ W2,
                             const float* __restrict__ b1,
                             float* __restrict__ outY, int N) {
    gemm_body<64, true>(X, W2, b1, outY, N, blockIdx.x);
}

// ---------------------------------------------------------------------------
// Gather core (at LTS cap; 4-way unroll, 2 accumulators)
// ---------------------------------------------------------------------------
__device__ __forceinline__ float4 gather_row(const int* __restrict__ cnt,
                                             const int* __restrict__ buck,
                                             const float* __restrict__ Y,
                                             int n, int c) {
    float4 a0 = __ldg((const float4*)(Y + (size_t)n * 64) + c);  // self term
    float4 a1 = make_float4(0.f, 0.f, 0.f, 0.f);
    int m = min(__ldg(&cnt[n]), CAP);
    const int* b = buck + (size_t)n * CAP;

    int j = 0;
    for (; j + 4 <= m; j += 4) {
        int s0 = __ldg(&b[j]);
        int s1 = __ldg(&b[j + 1]);
        int s2 = __ldg(&b[j + 2]);
        int s3 = __ldg(&b[j + 3]);
        float4 v0 = __ldg((const float4*)(Y + (size_t)s0 * 64) + c);
        float4 v1 = __ldg((const float4*)(Y + (size_t)s1 * 64) + c);
        float4 v2 = __ldg((const float4*)(Y + (size_t)s2 * 64) + c);
        float4 v3 = __ldg((const float4*)(Y + (size_t)s3 * 64) + c);
        a0.x += v0.x + v1.x;  a0.y += v0.y + v1.y;
        a0.z += v0.z + v1.z;  a0.w += v0.w + v1.w;
        a1.x += v2.x + v3.x;  a1.y += v2.y + v3.y;
        a1.z += v2.z + v3.z;  a1.w += v2.w + v3.w;
    }
    for (; j < m; ++j) {
        int s0 = __ldg(&b[j]);
        float4 v0 = __ldg((const float4*)(Y + (size_t)s0 * 64) + c);
        a0.x += v0.x; a0.y += v0.y; a0.z += v0.z; a0.w += v0.w;
    }
    a0.x += a1.x; a0.y += a1.y; a0.z += a1.z; a0.w += a1.w;
    return a0;
}

__global__ void gather_kernel(const int* __restrict__ cnt,
                              const int* __restrict__ buck,
                              const float* __restrict__ Y,
                              float* __restrict__ Agg,
                              int N) {
    int t = blockIdx.x * blockDim.x + threadIdx.x;
    int n = t >> 4;
    int c = t & 15;
    if (n >= N) return;
    float4 acc = gather_row(cnt, buck, Y, n, c);
    *((float4*)(Agg + (size_t)n * 64) + c) = acc;
}

// ---------------------------------------------------------------------------
// Fused layer-2 aggregation + MLP head
// ---------------------------------------------------------------------------
__global__ void gather_head_kernel(const int* __restrict__ cnt,
                                   const int* __restrict__ buck,
                                   const float* __restrict__ Y,
                                   const float* __restrict__ b2,
                                   const float* __restrict__ W3,
                                   const float* __restrict__ b3,
                                   const float* __restrict__ W4,
                                   const float* __restrict__ b4,
                                   float* __restrict__ out,
                                   int N) {
    __shared__ float W3s[64 * 16];
    __shared__ float b2s[64], b3s[16], W4s[16];
    __shared__ float h2s[16][64];        // 16 nodes per 256-thread block

    const int tid = threadIdx.x;
    for (int i = tid; i < 64 * 16; i += 256) W3s[i] = W3[i];
    if (tid < 64) b2s[tid] = b2[tid];
    if (tid < 16) { b3s[tid] = b3[tid]; W4s[tid] = W4[tid]; }
    __syncthreads();

    int t = blockIdx.x * 256 + tid;
    int n = t >> 4;
    int c = t & 15;                      // float4 column / W3 output index
    int g = tid >> 4;                    // node slot within block
    if (n >= N) return;

    float4 acc = gather_row(cnt, buck, Y, n, c);

    float4 h;
    h.x = fmaxf(acc.x + b2s[4 * c + 0], 0.f);
    h.y = fmaxf(acc.y + b2s[4 * c + 1], 0.f);
    h.z = fmaxf(acc.z + b2s[4 * c + 2], 0.f);
    h.w = fmaxf(acc.w + b2s[4 * c + 3], 0.f);
    *(float4*)(&h2s[g][4 * c]) = h;
    __syncwarp();

    float a3 = b3s[c];
    #pragma unroll 16
    for (int k = 0; k < 64; ++k)
        a3 += h2s[g][k] * W3s[k * 16 + c];
    float v = fmaxf(a3, 0.f) * W4s[c];

    #pragma unroll
    for (int off = 8; off > 0; off >>= 1)
        v += __shfl_xor_sync(0xffffffffu, v, off, 16);

    if (c == 0) out[n] = v + __ldg(&b4[0]);
}

// ---------------------------------------------------------------------------
extern "C" void kernel_launch(void* const* d_in, const int* in_sizes, int n_in,
                              void* d_out, int out_size) {
    const float* x  = (const float*)d_in[0];
    const int*   ei = (const int*)d_in[1];     // int32 (JAX x64 disabled)
    const float* W1 = (const float*)d_in[2];
    const float* b1 = (const float*)d_in[3];
    const float* W2 = (const float*)d_in[4];
    const float* b2 = (const float*)d_in[5];
    const float* W3 = (const float*)d_in[6];
    const float* b3 = (const float*)d_in[7];
    const float* W4 = (const float*)d_in[8];
    const float* b4 = (const float*)d_in[9];
    float* out = (float*)d_out;

    const int N = in_sizes[0] / 128;     // 100000
    const int E = in_sizes[1] / 2;       // 1600000

    float *bufY, *bufAgg;
    int *cnt, *buck;
    cudaGetSymbolAddress((void**)&bufY, g_bufY);
    cudaGetSymbolAddress((void**)&bufAgg, g_bufAgg);
    cudaGetSymbolAddress((void**)&cnt, g_cnt);
    cudaGetSymbolAddress((void**)&buck, g_buck);

    const int smem1 = (64 * (128 + 4) + 128 * 64) * (int)sizeof(float); // 66560
    const int smem2 = (64 * (64 + 4)  + 64 * 64)  * (int)sizeof(float); // 33792
    cudaFuncSetAttribute((const void*)gemm1_build_kernel,
                         cudaFuncAttributeMaxDynamicSharedMemorySize, smem1);
    cudaFuncSetAttribute((const void*)gemm2_kernel,
                         cudaFuncAttributeMaxDynamicSharedMemorySize, smem2);

    const int gb  = (N + 63) / 64;                             // 1563 gemm blocks
    const int bb  = (E + 255) / 256;                           // 6250 build blocks
    const int agb = (int)(((long long)N * 16 + 255) / 256);

    // zero degree counters (must precede build blocks)
    zero_cnt_kernel<<<(N + 255) / 256, 256>>>(cnt, N);
    // merged: gemm1 (FMA-bound) overlapped with bucket build (L2-atomic-bound)
    gemm1_build_kernel<<<gb + bb, 256, smem1>>>(x, W1, bufY, N, ei, cnt, buck, E, gb);
    // agg1 = y1 + gather(y1)
    gather_kernel<<<agb, 256>>>(cnt, buck, bufY, bufAgg, N);
    // y2 = relu(agg1+b1)@W2
    gemm2_kernel<<<gb, 256, smem2>>>(bufAgg, W2, b1, bufY, N);
    // fused: agg2 = y2 + gather(y2); head MLP -> out
    gather_head_kernel<<<agb, 256>>>(cnt, buck, bufY, b2, W3, b3, W4, b4, out, N);
}